// round 2
// baseline (speedup 1.0000x reference)
#include <cuda_runtime.h>

#define NB    4
#define QLEN  4096
#define HIDD  1024
#define NHEAD 16
#define HDIM  64
#define TXTN  77
#define IPTN  8
#define CDIM  768
#define ENCR  85   // TXT + IPT

// ---------------- scratch (no allocation allowed) ----------------
__device__ float g_Wq [HIDD*HIDD];
__device__ float g_Wk [CDIM*HIDD];
__device__ float g_Wv [CDIM*HIDD];
__device__ float g_Wo [HIDD*HIDD];
__device__ float g_q  [NB*QLEN*HIDD];
__device__ float g_hid[NB*QLEN*HIDD];
__device__ float g_kk [NB*TXTN*HIDD];
__device__ float g_vv [NB*TXTN*HIDD];
__device__ float g_ipk[NB*IPTN*HIDD];
__device__ float g_ipv[NB*IPTN*HIDD];
__device__ float g_ehs[NB*TXTN*CDIM];
__device__ float g_ip [NB*IPTN*CDIM];
__device__ float g_ipkS[NB*HIDD];
__device__ float g_w  [NB*QLEN];
__device__ float g_mm [2*NB];

// ---------------- fold rank-4 LoRA into weight ----------------
__global__ void fuse_w_kernel(const float* __restrict__ W,
                              const float* __restrict__ down,
                              const float* __restrict__ up,
                              float* __restrict__ out, int K)
{
    int idx = blockIdx.x * 256 + threadIdx.x;
    if (idx >= K * HIDD) return;
    int r = idx >> 10, c = idx & 1023;
    float acc = W[idx];
#pragma unroll
    for (int j = 0; j < 4; j++)
        acc = fmaf(down[r*4 + j], up[j*HIDD + c], acc);
    out[idx] = acc;
}

// ---------------- pack encoder slices contiguous ----------------
__global__ void pack_enc_kernel(const float* __restrict__ enc,
                                float* __restrict__ ehs,
                                float* __restrict__ ipb)
{
    int idx = blockIdx.x * 256 + threadIdx.x;
    const int n1 = NB*TXTN*CDIM;
    const int n2 = NB*IPTN*CDIM;
    if (idx < n1) {
        int b = idx / (TXTN*CDIM);
        int rem = idx - b*(TXTN*CDIM);
        int t = rem / CDIM, c = rem - t*CDIM;
        ehs[idx] = enc[((size_t)b*ENCR + t)*CDIM + c];
    } else if (idx < n1 + n2) {
        int k = idx - n1;
        int b = k / (IPTN*CDIM);
        int rem = k - b*(IPTN*CDIM);
        int t = rem / CDIM, c = rem - t*CDIM;
        ipb[k] = enc[((size_t)b*ENCR + TXTN + t)*CDIM + c];
    }
}

// ---------------- tiled fp32 GEMM: C[M,N] = A[M,K] @ B[K,N] (+bias) ----------------
// BM=BN=128, BK=8, 256 threads, 8x8 per thread. Row-guarded for M not mult of 128.
// N must be a multiple of 128, K a multiple of 8 (true for all calls here).
__global__ __launch_bounds__(256) void sgemm128(
    const float* __restrict__ A, const float* __restrict__ B,
    float* __restrict__ C, const float* __restrict__ bias,
    int M, int N, int K)
{
    __shared__ float As[8][128];
    __shared__ float Bs[8][128];
    const int tid = threadIdx.x;
    const int bx = blockIdx.x, by = blockIdx.y;
    const int tcol = tid & 15, trow = tid >> 4;
    const int a_row = tid >> 1, a_col = (tid & 1) << 2;
    const int b_row = tid >> 5, b_col = (tid & 31) << 2;

    const float* Ab = A + (size_t)by * 128 * K;
    const float* Bb = B + bx * 128;
    const int arow_g = by * 128 + a_row;
    const bool aval = (arow_g < M);

    float acc[8][8];
#pragma unroll
    for (int i = 0; i < 8; i++)
#pragma unroll
        for (int j = 0; j < 8; j++) acc[i][j] = 0.f;

    for (int k0 = 0; k0 < K; k0 += 8) {
        float4 av = aval ? *(const float4*)(Ab + (size_t)a_row*K + k0 + a_col)
                         : make_float4(0.f, 0.f, 0.f, 0.f);
        As[a_col + 0][a_row] = av.x;
        As[a_col + 1][a_row] = av.y;
        As[a_col + 2][a_row] = av.z;
        As[a_col + 3][a_row] = av.w;
        float4 bv = *(const float4*)(Bb + (size_t)(k0 + b_row)*N + b_col);
        *(float4*)&Bs[b_row][b_col] = bv;
        __syncthreads();
#pragma unroll
        for (int kk = 0; kk < 8; kk++) {
            float ra[8], rb[8];
            *(float4*)(ra)     = *(const float4*)&As[kk][trow*8];
            *(float4*)(ra + 4) = *(const float4*)&As[kk][trow*8 + 4];
            *(float4*)(rb)     = *(const float4*)&Bs[kk][tcol*8];
            *(float4*)(rb + 4) = *(const float4*)&Bs[kk][tcol*8 + 4];
#pragma unroll
            for (int i = 0; i < 8; i++)
#pragma unroll
                for (int j = 0; j < 8; j++)
                    acc[i][j] = fmaf(ra[i], rb[j], acc[i][j]);
        }
        __syncthreads();
    }

    const int rb0 = by*128 + trow*8;
    const int cb0 = bx*128 + tcol*8;
#pragma unroll
    for (int i = 0; i < 8; i++) {
        int r = rb0 + i;
        if (r >= M) continue;
#pragma unroll
        for (int j = 0; j < 8; j += 4) {
            float4 v = make_float4(acc[i][j], acc[i][j+1], acc[i][j+2], acc[i][j+3]);
            if (bias) {
                v.x += bias[cb0 + j + 0];
                v.y += bias[cb0 + j + 1];
                v.z += bias[cb0 + j + 2];
                v.w += bias[cb0 + j + 3];
            }
            *(float4*)(C + (size_t)r*N + cb0 + j) = v;
        }
    }
}

// ---------------- ipk token-sum: [B,8,1024] -> [B,1024] ----------------
__global__ void ipksum_kernel(const float* __restrict__ ipk, float* __restrict__ out)
{
    int idx = blockIdx.x * 256 + threadIdx.x;
    if (idx >= NB * HIDD) return;
    int b = idx >> 10, j = idx & 1023;
    float s = 0.f;
#pragma unroll
    for (int t = 0; t < IPTN; t++)
        s += ipk[((size_t)b*IPTN + t)*HIDD + j];
    out[idx] = s;
}

// ---------------- w[b,q] = scale * dot(q_full, ipkSum) ----------------
__global__ __launch_bounds__(256) void wsum_kernel(const float* __restrict__ qb,
                                                   const float* __restrict__ ipkS,
                                                   float* __restrict__ w)
{
    __shared__ float sk[HIDD];
    const int row0 = blockIdx.x * 8;          // 8 rows/block, same batch
    const int b = row0 / QLEN;
    for (int i = threadIdx.x; i < HIDD; i += 256) sk[i] = ipkS[b*HIDD + i];
    __syncthreads();
    const int warp = threadIdx.x >> 5, lane = threadIdx.x & 31;
    const int row = row0 + warp;
    const float* qr = qb + (size_t)row * HIDD;
    float s = 0.f;
#pragma unroll
    for (int i = 0; i < 32; i++)
        s = fmaf(qr[lane + 32*i], sk[lane + 32*i], s);
#pragma unroll
    for (int off = 16; off > 0; off >>= 1)
        s += __shfl_xor_sync(0xffffffffu, s, off);
    if (lane == 0) w[row] = 0.125f * s;
}

// ---------------- per-batch min/max of w ----------------
__global__ void minmax_kernel(const float* __restrict__ w, float* __restrict__ mm)
{
    __shared__ float smn[256], smx[256];
    const int b = blockIdx.x, tid = threadIdx.x;
    float mn = 1e30f, mx = -1e30f;
    for (int i = tid; i < QLEN; i += 256) {
        float v = w[b*QLEN + i];
        mn = fminf(mn, v); mx = fmaxf(mx, v);
    }
    smn[tid] = mn; smx[tid] = mx;
    __syncthreads();
    for (int s = 128; s > 0; s >>= 1) {
        if (tid < s) {
            smn[tid] = fminf(smn[tid], smn[tid + s]);
            smx[tid] = fmaxf(smx[tid], smx[tid + s]);
        }
        __syncthreads();
    }
    if (tid == 0) { mm[2*b] = smn[0]; mm[2*b + 1] = smx[0]; }
}

// ---------------- fused attention: text softmax-attn + IP attn + aw combine ----------------
// block = 128 threads, one thread per q row; block handles (b, h, 128 q rows)
__global__ __launch_bounds__(128) void attn_kernel(
    const float* __restrict__ qb,   // [B,Q,1024]
    const float* __restrict__ kk,   // [B,77,1024]
    const float* __restrict__ vv,
    const float* __restrict__ ipk,  // [B,8,1024]
    const float* __restrict__ ipv,
    const float* __restrict__ wbuf, // [B,Q]
    const float* __restrict__ mm,   // [B][min,max]
    float* __restrict__ hid)        // [B,Q,1024]
{
    __shared__ float smem[TXTN*HDIM*2 + IPTN*HDIM*2];   // 10880 floats = 43520 B
    float* sK  = smem;
    float* sV  = smem + TXTN*HDIM;
    float* sIK = smem + 2*TXTN*HDIM;
    float* sIV = sIK + IPTN*HDIM;

    const int tid = threadIdx.x;
    const int b = blockIdx.z, h = blockIdx.y, q0 = blockIdx.x * 128;

    const size_t kvbase = ((size_t)b*TXTN)*HIDD + h*HDIM;
    for (int i = tid; i < TXTN*HDIM; i += 128) {
        int t = i >> 6, d = i & 63;
        sK[i] = kk[kvbase + (size_t)t*HIDD + d];
        sV[i] = vv[kvbase + (size_t)t*HIDD + d];
    }
    const size_t ipbase = ((size_t)b*IPTN)*HIDD + h*HDIM;
    for (int i = tid; i < IPTN*HDIM; i += 128) {
        int t = i >> 6, d = i & 63;
        sIK[i] = ipk[ipbase + (size_t)t*HIDD + d];
        sIV[i] = ipv[ipbase + (size_t)t*HIDD + d];
    }
    __syncthreads();

    const int qi = q0 + tid;                       // q index within batch
    float4 q4[16];
    const float4* qp = (const float4*)(qb + ((size_t)b*QLEN + qi)*HIDD + h*HDIM);
#pragma unroll
    for (int i = 0; i < 16; i++) q4[i] = qp[i];

    // ---- text attention, online softmax with lazy rescale ----
    float m = -1e30f, l = 0.f;
    float4 o4[16];
#pragma unroll
    for (int i = 0; i < 16; i++) o4[i] = make_float4(0.f, 0.f, 0.f, 0.f);

    for (int t = 0; t < TXTN; t++) {
        const float4* kp = (const float4*)(sK + t*HDIM);
        float s = 0.f;
#pragma unroll
        for (int i = 0; i < 16; i++) {
            float4 kv = kp[i];
            s = fmaf(q4[i].x, kv.x, s); s = fmaf(q4[i].y, kv.y, s);
            s = fmaf(q4[i].z, kv.z, s); s = fmaf(q4[i].w, kv.w, s);
        }
        s *= 0.125f;
        if (s > m) {
            float c = __expf(m - s);
            l *= c;
#pragma unroll
            for (int i = 0; i < 16; i++) {
                o4[i].x *= c; o4[i].y *= c; o4[i].z *= c; o4[i].w *= c;
            }
            m = s;
        }
        float p = __expf(s - m);
        l += p;
        const float4* vp = (const float4*)(sV + t*HDIM);
#pragma unroll
        for (int i = 0; i < 16; i++) {
            float4 v = vp[i];
            o4[i].x = fmaf(p, v.x, o4[i].x); o4[i].y = fmaf(p, v.y, o4[i].y);
            o4[i].z = fmaf(p, v.z, o4[i].z); o4[i].w = fmaf(p, v.w, o4[i].w);
        }
    }
    const float inv_l = 1.f / l;

    // ---- IP attention (8 tokens, bbox mask) ----
    float sip[IPTN];
#pragma unroll
    for (int t = 0; t < IPTN; t++) {
        const float4* kp = (const float4*)(sIK + t*HDIM);
        float s = 0.f;
#pragma unroll
        for (int i = 0; i < 16; i++) {
            float4 kv = kp[i];
            s = fmaf(q4[i].x, kv.x, s); s = fmaf(q4[i].y, kv.y, s);
            s = fmaf(q4[i].z, kv.z, s); s = fmaf(q4[i].w, kv.w, s);
        }
        sip[t] = s * 0.125f;
    }
    const int gr = qi >> 6, gc = qi & 63;
    const int region = (gr < 32) ? ((gc < 32) ? 0 : -1)
                                 : ((gc >= 32) ? 1 : -1);
    if (region == 0) { sip[4] = sip[5] = sip[6] = sip[7] = -1e30f; }
    else if (region == 1) { sip[0] = sip[1] = sip[2] = sip[3] = -1e30f; }

    float m2 = -1e30f;
#pragma unroll
    for (int t = 0; t < IPTN; t++) m2 = fmaxf(m2, sip[t]);
    float p2[IPTN], sum2 = 0.f;
#pragma unroll
    for (int t = 0; t < IPTN; t++) { p2[t] = __expf(sip[t] - m2); sum2 += p2[t]; }

    // ---- aw gate ----
    const float wv  = wbuf[b*QLEN + qi];
    const float wmn = mm[2*b], wmx = mm[2*b + 1];
    float aw = (wv - wmn) / (wmx - wmn);
    aw = (aw < 0.3f) ? 0.f : aw;
    aw *= 0.5f;
    if (region >= 0) aw = aw * 2.f + 1.f;
    const float coeff = aw / sum2;

#pragma unroll
    for (int i = 0; i < 16; i++) {
        float4 acc = make_float4(0.f, 0.f, 0.f, 0.f);
#pragma unroll
        for (int t = 0; t < IPTN; t++) {
            float4 v = ((const float4*)(sIV + t*HDIM))[i];
            acc.x = fmaf(p2[t], v.x, acc.x); acc.y = fmaf(p2[t], v.y, acc.y);
            acc.z = fmaf(p2[t], v.z, acc.z); acc.w = fmaf(p2[t], v.w, acc.w);
        }
        o4[i].x = o4[i].x * inv_l + coeff * acc.x;
        o4[i].y = o4[i].y * inv_l + coeff * acc.y;
        o4[i].z = o4[i].z * inv_l + coeff * acc.z;
        o4[i].w = o4[i].w * inv_l + coeff * acc.w;
    }

    // ---- stage through smem (stride 68 to dodge bank conflicts), coalesced store ----
    __syncthreads();                // everyone done reading sK/sV/sIK/sIV
    float* so = smem;               // 128*68 = 8704 floats, fits in sK+sV region
#pragma unroll
    for (int i = 0; i < 16; i++)
        *(float4*)(so + tid*68 + i*4) = o4[i];
    __syncthreads();

    float* outp = hid + ((size_t)b*QLEN + q0)*HIDD + h*HDIM;
    for (int i4 = tid; i4 < 128*16; i4 += 128) {
        int r = i4 >> 4, c = i4 & 15;
        float4 v = *(const float4*)(so + r*68 + c*4);
        *(float4*)(outp + (size_t)r*HIDD + c*4) = v;
    }
}

// ---------------- host launcher ----------------
extern "C" void kernel_launch(void* const* d_in, const int* in_sizes, int n_in,
                              void* d_out, int out_size)
{
    const float* hs     = (const float*)d_in[0];
    const float* enc    = (const float*)d_in[1];
    const float* Wq     = (const float*)d_in[2];
    const float* Wk     = (const float*)d_in[3];
    const float* Wv     = (const float*)d_in[4];
    const float* Wo     = (const float*)d_in[5];
    const float* bo     = (const float*)d_in[6];
    const float* q_down = (const float*)d_in[7];
    const float* q_up   = (const float*)d_in[8];
    const float* k_down = (const float*)d_in[9];
    const float* k_up   = (const float*)d_in[10];
    const float* v_down = (const float*)d_in[11];
    const float* v_up   = (const float*)d_in[12];
    const float* o_down = (const float*)d_in[13];
    const float* o_up   = (const float*)d_in[14];
    const float* Wk_ip  = (const float*)d_in[15];
    const float* Wv_ip  = (const float*)d_in[16];
    float* out = (float*)d_out;

    float *pWq, *pWk, *pWv, *pWo, *pq, *phid, *pkk, *pvv, *pipk, *pipv;
    float *pehs, *pip, *pipkS, *pw, *pmm;
    cudaGetSymbolAddress((void**)&pWq,  g_Wq);
    cudaGetSymbolAddress((void**)&pWk,  g_Wk);
    cudaGetSymbolAddress((void**)&pWv,  g_Wv);
    cudaGetSymbolAddress((void**)&pWo,  g_Wo);
    cudaGetSymbolAddress((void**)&pq,   g_q);
    cudaGetSymbolAddress((void**)&phid, g_hid);
    cudaGetSymbolAddress((void**)&pkk,  g_kk);
    cudaGetSymbolAddress((void**)&pvv,  g_vv);
    cudaGetSymbolAddress((void**)&pipk, g_ipk);
    cudaGetSymbolAddress((void**)&pipv, g_ipv);
    cudaGetSymbolAddress((void**)&pehs, g_ehs);
    cudaGetSymbolAddress((void**)&pip,  g_ip);
    cudaGetSymbolAddress((void**)&pipkS,g_ipkS);
    cudaGetSymbolAddress((void**)&pw,   g_w);
    cudaGetSymbolAddress((void**)&pmm,  g_mm);

    // 1) fold LoRA into effective weights
    fuse_w_kernel<<<(HIDD*HIDD + 255)/256, 256>>>(Wq, q_down, q_up, pWq, HIDD);
    fuse_w_kernel<<<(CDIM*HIDD + 255)/256, 256>>>(Wk, k_down, k_up, pWk, CDIM);
    fuse_w_kernel<<<(CDIM*HIDD + 255)/256, 256>>>(Wv, v_down, v_up, pWv, CDIM);
    fuse_w_kernel<<<(HIDD*HIDD + 255)/256, 256>>>(Wo, o_down, o_up, pWo, HIDD);

    // 2) pack encoder slices
    pack_enc_kernel<<<((NB*TXTN + NB*IPTN)*CDIM + 255)/256, 256>>>(enc, pehs, pip);

    // 3) projections
    sgemm128<<<dim3(HIDD/128, NB*QLEN/128), 256>>>(hs,   pWq,   pq,   nullptr, NB*QLEN, HIDD, HIDD);
    sgemm128<<<dim3(HIDD/128, 3),           256>>>(pehs, pWk,   pkk,  nullptr, NB*TXTN, HIDD, CDIM);
    sgemm128<<<dim3(HIDD/128, 3),           256>>>(pehs, pWv,   pvv,  nullptr, NB*TXTN, HIDD, CDIM);
    sgemm128<<<dim3(HIDD/128, 1),           256>>>(pip,  Wk_ip, pipk, nullptr, NB*IPTN, HIDD, CDIM);
    sgemm128<<<dim3(HIDD/128, 1),           256>>>(pip,  Wv_ip, pipv, nullptr, NB*IPTN, HIDD, CDIM);

    // 4) w = scale * q_full . (sum_t ipk), then per-batch min/max
    ipksum_kernel<<<(NB*HIDD + 255)/256, 256>>>(pipk, pipkS);
    wsum_kernel<<<NB*QLEN/8, 256>>>(pq, pipkS, pw);
    minmax_kernel<<<NB, 256>>>(pw, pmm);

    // 5) fused text + IP attention -> hid
    attn_kernel<<<dim3(QLEN/128, NHEAD, NB), 128>>>(pq, pkk, pvv, pipk, pipv, pw, pmm, phid);

    // 6) output projection (+bias) -> d_out
    sgemm128<<<dim3(HIDD/128, NB*QLEN/128), 256>>>(phid, pWo, out, bo, NB*QLEN, HIDD, HIDD);
}